// round 7
// baseline (speedup 1.0000x reference)
#include <cuda_runtime.h>
#include <math.h>

#define HH 512
#define WW 512
#define BN 32
#define CN 3
#define HW (HH * WW)

#define TILE  8                 // output rows per block
#define BAND  16                // staged source rows  [y0-4, y0+11]
#define PITCH 528               // staged cols [-8, 519], 16B-aligned
#define SM_CH (BAND * PITCH)    // floats per channel in smem

// Scratch (allocation-free rule: __device__ globals)
__device__ float g_Minv[BN * 9];
__device__ float g_A[HW];          // L * 0.85
__device__ float g_Z[CN * HW];     // min(z1,z2) * 0.15

// ---------------------------------------------------------------------------
// Closed-form homography (Heckbert square->quad) + 3x3 inverse, fp64.
// ---------------------------------------------------------------------------
__device__ __forceinline__ void solve_one(int b, const float* __restrict__ dst_off) {
    const double bu[4] = {0.0, 512.0, 512.0, 0.0};
    const double bv[4] = {0.0, 0.0, 512.0, 512.0};
    double u[4], v[4];
    #pragma unroll
    for (int i = 0; i < 4; i++) {
        u[i] = bu[i] + (double)dst_off[(b * 4 + i) * 2 + 0];
        v[i] = bv[i] + (double)dst_off[(b * 4 + i) * 2 + 1];
    }
    double sx  = u[0] - u[1] + u[2] - u[3];
    double sy  = v[0] - v[1] + v[2] - v[3];
    double dx1 = u[1] - u[2], dx2 = u[3] - u[2];
    double dy1 = v[1] - v[2], dy2 = v[3] - v[2];
    double den = dx1 * dy2 - dx2 * dy1;
    double g = (sx * dy2 - dx2 * sy) / den;
    double h = (dx1 * sy - sx * dy1) / den;
    double a = u[1] - u[0] + g * u[1];
    double bb = u[3] - u[0] + h * u[3];
    double c = u[0];
    double d = v[1] - v[0] + g * v[1];
    double e = v[3] - v[0] + h * v[3];
    double f = v[0];
    const double is = 1.0 / 511.0;
    double m[9] = {a * is, bb * is, c,
                   d * is, e  * is, f,
                   g * is, h  * is, 1.0};

    double det = m[0] * (m[4] * m[8] - m[5] * m[7])
               - m[1] * (m[3] * m[8] - m[5] * m[6])
               + m[2] * (m[3] * m[7] - m[4] * m[6]);
    double id = 1.0 / det;

    float* o = g_Minv + b * 9;
    o[0] = (float)( (m[4] * m[8] - m[5] * m[7]) * id);
    o[1] = (float)(-(m[1] * m[8] - m[2] * m[7]) * id);
    o[2] = (float)( (m[1] * m[5] - m[2] * m[4]) * id);
    o[3] = (float)(-(m[3] * m[8] - m[5] * m[6]) * id);
    o[4] = (float)( (m[0] * m[8] - m[2] * m[6]) * id);
    o[5] = (float)(-(m[0] * m[5] - m[2] * m[3]) * id);
    o[6] = (float)( (m[3] * m[7] - m[4] * m[6]) * id);
    o[7] = (float)(-(m[0] * m[7] - m[1] * m[6]) * id);
    o[8] = (float)( (m[0] * m[4] - m[1] * m[3]) * id);
}

// ---------------------------------------------------------------------------
// Fused setup: light mask (x0.85) + moire (x0.15) + per-batch homographies.
// ---------------------------------------------------------------------------
__global__ void setup_kernel(const float* __restrict__ dst_off,
                             const float* __restrict__ ab,
                             const float* __restrict__ centers,
                             const int* __restrict__ cflag,
                             const int* __restrict__ direction,
                             const int* __restrict__ light_xy,
                             const int* __restrict__ theta) {
    if (blockIdx.x == gridDim.x - 1) {
        int b = threadIdx.x;
        if (b < BN) solve_one(b, dst_off);
        return;
    }
    int idx = blockIdx.x * blockDim.x + threadIdx.x;
    int i = idx / WW;   // row
    int j = idx % WW;   // col

    float a = ab[0], bb = ab[1];
    float L;
    if (cflag[0] == 0) {
        int k = direction[0] - 1;  // rot90 count {0,1,2,3}
        int t = (k == 0) ? i : (k == 1) ? j : (k == 2) ? (HH - 1 - i) : (WW - 1 - j);
        L = -((bb - a) / (float)(HH - 1)) * ((float)t - (float)WW) + a;
    } else {
        float x = (float)light_xy[0], y = (float)light_xy[1];
        float d0 = sqrtf(x * x + y * y);
        float d1 = sqrtf((x - 255.f) * (x - 255.f) + y * y);
        float d2 = sqrtf(x * x + (y - 255.f) * (y - 255.f));
        float d3 = sqrtf((x - 512.f) * (x - 512.f) + (y - 512.f) * (y - 512.f));
        float ml = fmaxf(fmaxf(d0, d1), fmaxf(d2, d3));
        float dx = (float)i - x, dy = (float)j - y;
        float dist = sqrtf(dx * dx + dy * dy);
        L = dist / ml * (a - bb) + bb;
    }
    g_A[idx] = L * 0.85f;

    const float TWO_PI = 6.283185307179586f;
    float xg = (float)(i + 1), yg = (float)(j + 1);
    #pragma unroll
    for (int k = 0; k < 3; k++) {
        float cx = centers[k * 2 + 0], cy = centers[k * 2 + 1];
        float th = (float)theta[k] * 0.017453292519943295f;
        float cth = __cosf(th), sth = __sinf(th);
        float dx = xg - cx, dy = yg - cy;
        float dist = sqrtf(dx * dx + dy * dy);
        float f1 = dist - floorf(dist);               // period-1 reduction
        float t2 = cth * xg + sth * yg;
        float f2 = t2 - floorf(t2);
        float z1 = 0.5f + 0.5f * __cosf(TWO_PI * f1);
        float z2 = 0.5f + 0.5f * __cosf(TWO_PI * f2);
        g_Z[k * HW + idx] = fminf(z1, z2) * 0.15f;
    }
}

// ---------------------------------------------------------------------------
// Fused warp + blend, smem-staged gather.
// Block = 512 threads = 8 output rows x 512 cols of one batch image.
// 1) Stage source band rows [y0-4, y0+11], cols [-8, 520) x 3ch into smem
//    (zero-padded outside the image) with coalesced float4 loads.
// 2) Per pixel: bilinear from smem (12 conflict-free LDS, no predicates --
//    zero padding implements the border), blend, coalesced scalar store.
//    A never-taken global-gather fallback guards the band bound.
// ---------------------------------------------------------------------------
extern __shared__ float s_img[];   // 3 * BAND * PITCH floats = 101376 B

__global__ void __launch_bounds__(512) main_kernel(const float* __restrict__ img,
                                                   const float* __restrict__ noise,
                                                   float* __restrict__ out) {
    int y0 = blockIdx.x * TILE;
    int b  = blockIdx.y;
    int t  = threadIdx.x;

    // ---- stage band into smem ----
    const int NV = 3 * BAND * (PITCH / 4);          // 6336 float4 slots
    for (int idx = t; idx < NV; idx += 512) {
        int ch  = idx / (BAND * (PITCH / 4));
        int rem = idx - ch * (BAND * (PITCH / 4));
        int r   = rem / (PITCH / 4);
        int c4  = rem - r * (PITCH / 4);
        int gr   = y0 - 4 + r;
        int gcol = c4 * 4 - 8;
        float4 v = make_float4(0.f, 0.f, 0.f, 0.f);
        if ((unsigned)gr < HH && (unsigned)gcol < WW) {
            v = *(const float4*)(img + (((size_t)(b * 3 + ch) * HH + gr) << 9) + gcol);
        }
        *(float4*)(s_img + ch * SM_CH + r * PITCH + c4 * 4) = v;
    }
    __syncthreads();

    const float* Mi = g_Minv + b * 9;
    float m00 = Mi[0], m01 = Mi[1], m02 = Mi[2];
    float m10 = Mi[3], m11 = Mi[4], m12 = Mi[5];
    float m20 = Mi[6], m21 = Mi[7], m22 = Mi[8];

    const float kn = 0.031622776601683794f;  // sqrt(0.001)
    int x = t;
    float fx = (float)x;

    #pragma unroll
    for (int q = 0; q < TILE; q++) {
        int y = y0 + q;
        float fy = (float)y;
        float c0 = m01 * fy + m02;
        float c1 = m11 * fy + m12;
        float c2 = m21 * fy + m22;

        float inv = 1.0f / (m20 * fx + c2);
        float xs = (m00 * fx + c0) * inv;
        float ys = (m10 * fx + c1) * inv;
        float xf = floorf(xs), yf = floorf(ys);
        float wx = xs - xf, wy = ys - yf;
        int ix = (int)xf, iy = (int)yf;
        float w00 = (1.f - wx) * (1.f - wy);
        float w01 = wx * (1.f - wy);
        float w10 = (1.f - wx) * wy;
        float w11 = wx * wy;

        int rl = iy - (y0 - 4);      // local band row
        int cl = ix + 8;             // local band col
        bool ok = ((unsigned)rl < (BAND - 1)) && ((unsigned)cl < (PITCH - 1));

        float res[3];
        if (ok) {
            int sidx = rl * PITCH + cl;
            #pragma unroll
            for (int ch = 0; ch < 3; ch++) {
                const float* sp = s_img + ch * SM_CH + sidx;
                res[ch] = sp[0] * w00 + sp[1] * w01
                        + sp[PITCH] * w10 + sp[PITCH + 1] * w11;
            }
        } else {
            // never-taken safety path: full global bilinear with predicates
            bool vx0 = ((unsigned)ix < WW);
            bool vx1 = ((unsigned)(ix + 1) < WW);
            bool vy0 = ((unsigned)iy < HH);
            bool vy1 = ((unsigned)(iy + 1) < HH);
            bool p00 = vx0 && vy0, p01 = vx1 && vy0;
            bool p10 = vx0 && vy1, p11 = vx1 && vy1;
            int i00 = iy * WW + ix;
            const float* base = img + (size_t)b * (3 * HW);
            #pragma unroll
            for (int ch = 0; ch < 3; ch++) {
                const float* pp = base + ch * HW + i00;
                float v00 = p00 ? __ldg(pp)          : 0.f;
                float v01 = p01 ? __ldg(pp + 1)      : 0.f;
                float v10 = p10 ? __ldg(pp + WW)     : 0.f;
                float v11 = p11 ? __ldg(pp + WW + 1) : 0.f;
                res[ch] = v00 * w00 + v01 * w01 + v10 * w10 + v11 * w11;
            }
        }

        // blend + store (all lane-consecutive -> coalesced)
        float Av = __ldg(g_A + (size_t)y * WW + x);
        #pragma unroll
        for (int ch = 0; ch < 3; ch++) {
            size_t off = ((size_t)(b * 3 + ch) * HH + y) * WW + x;
            float nv = __ldcs(noise + off);
            float zv = __ldg(g_Z + ((size_t)ch * HH + y) * WW + x);
            __stcs(out + off, res[ch] * Av + zv + kn * nv);
        }
    }
}

// ---------------------------------------------------------------------------
extern "C" void kernel_launch(void* const* d_in, const int* in_sizes, int n_in,
                              void* d_out, int out_size) {
    const float* image    = (const float*)d_in[0];
    const float* dst_off  = (const float*)d_in[1];
    const float* ab       = (const float*)d_in[2];
    const float* centers  = (const float*)d_in[3];
    const float* noise    = (const float*)d_in[4];
    const int*   c        = (const int*)d_in[5];
    const int*   direction= (const int*)d_in[6];
    const int*   light_xy = (const int*)d_in[7];
    const int*   theta    = (const int*)d_in[8];
    float* out = (float*)d_out;

    const int smem_bytes = 3 * SM_CH * (int)sizeof(float);   // 101376
    static bool attr_set = false;
    if (!attr_set) {
        cudaFuncSetAttribute(main_kernel,
                             cudaFuncAttributeMaxDynamicSharedMemorySize,
                             smem_bytes);
        attr_set = true;
    }

    setup_kernel<<<HW / 256 + 1, 256>>>(dst_off, ab, centers, c,
                                        direction, light_xy, theta);
    dim3 grid(HH / TILE, BN);   // 64 x 32 blocks; same-b adjacent tiles -> L2 reuse
    main_kernel<<<grid, 512, smem_bytes>>>(image, noise, out);
}

// round 8
// speedup vs baseline: 2.1014x; 2.1014x over previous
#include <cuda_runtime.h>
#include <math.h>
#include <stdint.h>

#define HH 512
#define WW 512
#define BN 32
#define CN 3
#define HW (HH * WW)

// Scratch (allocation-free rule: __device__ globals)
__device__ float g_Minv[BN * 9];
__device__ float g_A[HW];          // L * 0.85
__device__ float g_Z[CN * HW];     // min(z1,z2) * 0.15

// ---------------------------------------------------------------------------
// Closed-form homography (Heckbert square->quad) + 3x3 inverse, fp64.
// ---------------------------------------------------------------------------
__device__ __forceinline__ void solve_one(int b, const float* __restrict__ dst_off) {
    const double bu[4] = {0.0, 512.0, 512.0, 0.0};
    const double bv[4] = {0.0, 0.0, 512.0, 512.0};
    double u[4], v[4];
    #pragma unroll
    for (int i = 0; i < 4; i++) {
        u[i] = bu[i] + (double)dst_off[(b * 4 + i) * 2 + 0];
        v[i] = bv[i] + (double)dst_off[(b * 4 + i) * 2 + 1];
    }
    double sx  = u[0] - u[1] + u[2] - u[3];
    double sy  = v[0] - v[1] + v[2] - v[3];
    double dx1 = u[1] - u[2], dx2 = u[3] - u[2];
    double dy1 = v[1] - v[2], dy2 = v[3] - v[2];
    double den = dx1 * dy2 - dx2 * dy1;
    double g = (sx * dy2 - dx2 * sy) / den;
    double h = (dx1 * sy - sx * dy1) / den;
    double a = u[1] - u[0] + g * u[1];
    double bb = u[3] - u[0] + h * u[3];
    double c = u[0];
    double d = v[1] - v[0] + g * v[1];
    double e = v[3] - v[0] + h * v[3];
    double f = v[0];
    const double is = 1.0 / 511.0;
    double m[9] = {a * is, bb * is, c,
                   d * is, e  * is, f,
                   g * is, h  * is, 1.0};

    double det = m[0] * (m[4] * m[8] - m[5] * m[7])
               - m[1] * (m[3] * m[8] - m[5] * m[6])
               + m[2] * (m[3] * m[7] - m[4] * m[6]);
    double id = 1.0 / det;

    float* o = g_Minv + b * 9;
    o[0] = (float)( (m[4] * m[8] - m[5] * m[7]) * id);
    o[1] = (float)(-(m[1] * m[8] - m[2] * m[7]) * id);
    o[2] = (float)( (m[1] * m[5] - m[2] * m[4]) * id);
    o[3] = (float)(-(m[3] * m[8] - m[5] * m[6]) * id);
    o[4] = (float)( (m[0] * m[8] - m[2] * m[6]) * id);
    o[5] = (float)(-(m[0] * m[5] - m[2] * m[3]) * id);
    o[6] = (float)( (m[3] * m[7] - m[4] * m[6]) * id);
    o[7] = (float)(-(m[0] * m[7] - m[1] * m[6]) * id);
    o[8] = (float)( (m[0] * m[4] - m[1] * m[3]) * id);
}

// ---------------------------------------------------------------------------
// Fused setup: light mask (x0.85) + moire (x0.15) + per-batch homographies.
// ---------------------------------------------------------------------------
__global__ void setup_kernel(const float* __restrict__ dst_off,
                             const float* __restrict__ ab,
                             const float* __restrict__ centers,
                             const int* __restrict__ cflag,
                             const int* __restrict__ direction,
                             const int* __restrict__ light_xy,
                             const int* __restrict__ theta) {
    if (blockIdx.x == gridDim.x - 1) {
        int b = threadIdx.x;
        if (b < BN) solve_one(b, dst_off);
        return;
    }
    int idx = blockIdx.x * blockDim.x + threadIdx.x;
    int i = idx / WW;   // row
    int j = idx % WW;   // col

    float a = ab[0], bb = ab[1];
    float L;
    if (cflag[0] == 0) {
        int k = direction[0] - 1;  // rot90 count {0,1,2,3}
        int t = (k == 0) ? i : (k == 1) ? j : (k == 2) ? (HH - 1 - i) : (WW - 1 - j);
        L = -((bb - a) / (float)(HH - 1)) * ((float)t - (float)WW) + a;
    } else {
        float x = (float)light_xy[0], y = (float)light_xy[1];
        float d0 = sqrtf(x * x + y * y);
        float d1 = sqrtf((x - 255.f) * (x - 255.f) + y * y);
        float d2 = sqrtf(x * x + (y - 255.f) * (y - 255.f));
        float d3 = sqrtf((x - 512.f) * (x - 512.f) + (y - 512.f) * (y - 512.f));
        float ml = fmaxf(fmaxf(d0, d1), fmaxf(d2, d3));
        float dx = (float)i - x, dy = (float)j - y;
        float dist = sqrtf(dx * dx + dy * dy);
        L = dist / ml * (a - bb) + bb;
    }
    g_A[idx] = L * 0.85f;

    const float TWO_PI = 6.283185307179586f;
    float xg = (float)(i + 1), yg = (float)(j + 1);
    #pragma unroll
    for (int k = 0; k < 3; k++) {
        float cx = centers[k * 2 + 0], cy = centers[k * 2 + 1];
        float th = (float)theta[k] * 0.017453292519943295f;
        float cth = __cosf(th), sth = __sinf(th);
        float dx = xg - cx, dy = yg - cy;
        float dist = sqrtf(dx * dx + dy * dy);
        float f1 = dist - floorf(dist);               // period-1 reduction
        float t2 = cth * xg + sth * yg;
        float f2 = t2 - floorf(t2);
        float z1 = 0.5f + 0.5f * __cosf(TWO_PI * f1);
        float z2 = 0.5f + 0.5f * __cosf(TWO_PI * f2);
        g_Z[k * HW + idx] = fminf(z1, z2) * 0.15f;
    }
}

// ---------------------------------------------------------------------------
// Fused warp + blend (R4 structure). Block = 128 threads = one (b, y) row.
// The 3x2KB noise rows (the only DRAM-latency loads in phase 2) are fetched
// via cp.async.bulk into smem, issued BEFORE phase 1 — the bulk path bypasses
// the per-thread L1tex wavefront queue, leaving it to the gathers, and the
// DRAM latency hides under phase-1 work. Occupancy stays 16 blocks/SM
// (smem 12.3KB).
// ---------------------------------------------------------------------------
__global__ void __launch_bounds__(128) main_kernel(const float* __restrict__ img,
                                                   const float* __restrict__ noise,
                                                   float* __restrict__ out) {
    __shared__ float sres[3][WW];
    __shared__ float snoise[3][WW];
    __shared__ uint64_t smbar;

    int b = blockIdx.z;
    int y = blockIdx.y;
    int tid = threadIdx.x;

    // mbarrier init (one thread), then make it visible block-wide
    uint32_t mbar_addr;
    {
        uint64_t* p = &smbar;
        asm("{ .reg .u64 t; cvta.to.shared.u64 t, %1; cvt.u32.u64 %0, t; }"
            : "=r"(mbar_addr) : "l"(p));
    }
    if (tid == 0) {
        asm volatile("mbarrier.init.shared.b64 [%0], 1;" :: "r"(mbar_addr) : "memory");
    }
    __syncthreads();

    // kick off async noise row copies (3 x 2KB)
    if (tid == 0) {
        asm volatile("mbarrier.arrive.expect_tx.shared.b64 _, [%0], %1;"
                     :: "r"(mbar_addr), "r"(3 * WW * 4) : "memory");
        #pragma unroll
        for (int ch = 0; ch < 3; ch++) {
            const float* src = noise + ((size_t)(b * 3 + ch) * HH + y) * WW;
            uint32_t dst;
            {
                float* p = &snoise[ch][0];
                asm("{ .reg .u64 t; cvta.to.shared.u64 t, %1; cvt.u32.u64 %0, t; }"
                    : "=r"(dst) : "l"(p));
            }
            asm volatile(
                "cp.async.bulk.shared::cta.global.mbarrier::complete_tx::bytes "
                "[%0], [%1], %2, [%3];"
                :: "r"(dst), "l"(src), "r"(WW * 4), "r"(mbar_addr) : "memory");
        }
    }

    // ---- phase 1: gather (R4 laning: x = p*128 + tid) ----
    const float* Mi = g_Minv + b * 9;
    float m00 = Mi[0], m01 = Mi[1], m02 = Mi[2];
    float m10 = Mi[3], m11 = Mi[4], m12 = Mi[5];
    float m20 = Mi[6], m21 = Mi[7], m22 = Mi[8];
    float fy = (float)y;
    float ftid = (float)tid;
    // numerators/denominator are linear in x: start at x = tid, step 128
    float nx = m00 * ftid + (m01 * fy + m02);
    float ny = m10 * ftid + (m11 * fy + m12);
    float nd = m20 * ftid + (m21 * fy + m22);
    const float sx = m00 * 128.f, sy2 = m10 * 128.f, sd = m20 * 128.f;
    const float* base = img + (size_t)b * (3 * HW);

    #pragma unroll
    for (int p = 0; p < 4; p++) {
        int x = p * 128 + tid;
        float inv = 1.0f / nd;
        float xs = nx * inv;
        float ys = ny * inv;
        nx += sx; ny += sy2; nd += sd;

        float xf = floorf(xs), yf = floorf(ys);
        float wx = xs - xf, wy = ys - yf;
        int ix = (int)xf, iy = (int)yf;
        bool vx0 = ((unsigned)ix < WW);
        bool vx1 = ((unsigned)(ix + 1) < WW);
        bool vy0 = ((unsigned)iy < HH);
        bool vy1 = ((unsigned)(iy + 1) < HH);
        bool p00 = vx0 && vy0, p01 = vx1 && vy0;
        bool p10 = vx0 && vy1, p11 = vx1 && vy1;
        float w00 = (1.f - wx) * (1.f - wy);
        float w01 = wx * (1.f - wy);
        float w10 = (1.f - wx) * wy;
        float w11 = wx * wy;
        int i00 = iy * WW + ix;   // raw; dereferenced only when predicate true

        #pragma unroll
        for (int ch = 0; ch < 3; ch++) {
            const float* pp = base + ch * HW + i00;
            float v00 = p00 ? __ldg(pp)          : 0.f;
            float v01 = p01 ? __ldg(pp + 1)      : 0.f;
            float v10 = p10 ? __ldg(pp + WW)     : 0.f;
            float v11 = p11 ? __ldg(pp + WW + 1) : 0.f;
            sres[ch][x] = v00 * w00 + v01 * w01 + v10 * w10 + v11 * w11;
        }
    }

    __syncthreads();                                   // sres ready
    // wait for bulk noise (phase 0)
    {
        uint32_t done;
        asm volatile(
            "{\n\t.reg .pred p;\n\t"
            "mbarrier.try_wait.parity.shared.b64 p, [%1], 0;\n\t"
            "selp.b32 %0, 1, 0, p;\n\t}"
            : "=r"(done) : "r"(mbar_addr) : "memory");
        while (!done) {
            asm volatile(
                "{\n\t.reg .pred p;\n\t"
                "mbarrier.try_wait.parity.shared.b64 p, [%1], 0;\n\t"
                "selp.b32 %0, 1, 0, p;\n\t}"
                : "=r"(done) : "r"(mbar_addr) : "memory");
        }
    }

    // ---- phase 2: vectorized blend (x0 = 4*tid) ----
    const float kn = 0.031622776601683794f;  // sqrt(0.001)
    int x0 = tid * 4;
    float4 av = *(const float4*)(g_A + (size_t)y * WW + x0);

    #pragma unroll
    for (int ch = 0; ch < 3; ch++) {
        float4 nv = *(const float4*)(&snoise[ch][x0]);
        float4 zv = *(const float4*)(g_Z + ((size_t)ch * HH + y) * WW + x0);
        float4 rv = *(const float4*)(&sres[ch][x0]);
        float4 ov;
        ov.x = rv.x * av.x + zv.x + kn * nv.x;
        ov.y = rv.y * av.y + zv.y + kn * nv.y;
        ov.z = rv.z * av.z + zv.z + kn * nv.z;
        ov.w = rv.w * av.w + zv.w + kn * nv.w;
        __stcs((float4*)(out + ((size_t)(b * 3 + ch) * HH + y) * WW + x0), ov);
    }
}

// ---------------------------------------------------------------------------
extern "C" void kernel_launch(void* const* d_in, const int* in_sizes, int n_in,
                              void* d_out, int out_size) {
    const float* image    = (const float*)d_in[0];
    const float* dst_off  = (const float*)d_in[1];
    const float* ab       = (const float*)d_in[2];
    const float* centers  = (const float*)d_in[3];
    const float* noise    = (const float*)d_in[4];
    const int*   c        = (const int*)d_in[5];
    const int*   direction= (const int*)d_in[6];
    const int*   light_xy = (const int*)d_in[7];
    const int*   theta    = (const int*)d_in[8];
    float* out = (float*)d_out;

    setup_kernel<<<HW / 256 + 1, 256>>>(dst_off, ab, centers, c,
                                        direction, light_xy, theta);
    dim3 grid(1, HH, BN);
    main_kernel<<<grid, 128>>>(image, noise, out);
}